// round 3
// baseline (speedup 1.0000x reference)
#include <cuda_runtime.h>

// Group ZCA whitening: x (64, 256, 56, 56) fp32, 64 groups of 4 channels.
// Pass 1: per-(group,batch) block computes partial sums + 10 raw second moments.
// Pass 2: per-group reduce + 4x4 symmetric Jacobi eigensolve (fp64) -> W, bias.
// Pass 3: out[b,c,s] = sum_j W[g][i][j]*x[b,gj,s] - bias[g][i].
//
// R2 (re-bench; prior attempt hit infra failure): grid swapped to (g fastest)
// for contiguous inter-block addresses; spatial loop fully unrolled (3 iters +
// 16-thread tail) with front-batched LDG.128 pairs to raise MLP.

#define NB   64      // batches
#define NG   64      // groups
#define NCH  256     // channels
#define SP   3136    // 56*56
#define SP4  784     // SP / 4
#define EPSF 1e-3

__device__ float g_part[NG * NB * 14];   // [group][batch][4 sums + 10 moments]
__device__ float g_W[NG * 16];
__device__ float g_bias[NG * 4];

// ---------------------------------------------------------------------------
// Pass 1: stats. grid (NG, NB), 256 threads.
// ---------------------------------------------------------------------------
__device__ __forceinline__ void acc_stats(float4 a, float4 e, float4 f, float4 h,
                                          float* v) {
    v[0]  += a.x + a.y + a.z + a.w;
    v[1]  += e.x + e.y + e.z + e.w;
    v[2]  += f.x + f.y + f.z + f.w;
    v[3]  += h.x + h.y + h.z + h.w;
    v[4]  += a.x*a.x + a.y*a.y + a.z*a.z + a.w*a.w;
    v[5]  += a.x*e.x + a.y*e.y + a.z*e.z + a.w*e.w;
    v[6]  += a.x*f.x + a.y*f.y + a.z*f.z + a.w*f.w;
    v[7]  += a.x*h.x + a.y*h.y + a.z*h.z + a.w*h.w;
    v[8]  += e.x*e.x + e.y*e.y + e.z*e.z + e.w*e.w;
    v[9]  += e.x*f.x + e.y*f.y + e.z*f.z + e.w*f.w;
    v[10] += e.x*h.x + e.y*h.y + e.z*h.z + e.w*h.w;
    v[11] += f.x*f.x + f.y*f.y + f.z*f.z + f.w*f.w;
    v[12] += f.x*h.x + f.y*h.y + f.z*h.z + f.w*h.w;
    v[13] += h.x*h.x + h.y*h.y + h.z*h.z + h.w*h.w;
}

__global__ __launch_bounds__(256) void stats_kernel(const float* __restrict__ x) {
    const int g = blockIdx.x;
    const int b = blockIdx.y;
    const int tid = threadIdx.x;
    const size_t base = ((size_t)b * NCH + (size_t)g * 4) * SP;
    const float4* __restrict__ c0 = (const float4*)(x + base);
    const float4* __restrict__ c1 = c0 + SP4;
    const float4* __restrict__ c2 = c0 + 2 * SP4;
    const float4* __restrict__ c3 = c0 + 3 * SP4;

    float v[14];
    #pragma unroll
    for (int k = 0; k < 14; k++) v[k] = 0.f;

    // iterations 0 and 1 front-batched (8 independent LDG.128)
    {
        const int i0 = tid, i1 = tid + 256;
        float4 a0 = c0[i0], e0 = c1[i0], f0 = c2[i0], h0 = c3[i0];
        float4 a1 = c0[i1], e1 = c1[i1], f1 = c2[i1], h1 = c3[i1];
        acc_stats(a0, e0, f0, h0, v);
        acc_stats(a1, e1, f1, h1, v);
    }
    // iteration 2 (full)
    {
        const int i2 = tid + 512;
        float4 a = c0[i2], e = c1[i2], f = c2[i2], h = c3[i2];
        acc_stats(a, e, f, h, v);
    }
    // tail: 784 - 768 = 16 elements
    if (tid < 16) {
        const int i3 = tid + 768;
        float4 a = c0[i3], e = c1[i3], f = c2[i3], h = c3[i3];
        acc_stats(a, e, f, h, v);
    }

    const int lane = tid & 31;
    const int warp = tid >> 5;
    #pragma unroll
    for (int k = 0; k < 14; k++) {
        #pragma unroll
        for (int o = 16; o > 0; o >>= 1)
            v[k] += __shfl_down_sync(0xffffffffu, v[k], o);
    }

    __shared__ float sm[8][14];
    if (lane == 0) {
        #pragma unroll
        for (int k = 0; k < 14; k++) sm[warp][k] = v[k];
    }
    __syncthreads();
    if (tid < 14) {
        float t = 0.f;
        #pragma unroll
        for (int w = 0; w < 8; w++) t += sm[w][tid];
        g_part[((size_t)g * NB + b) * 14 + tid] = t;
    }
}

// ---------------------------------------------------------------------------
// Pass 2: per-group reduce + 4x4 Jacobi eigensolve. grid (NG), 64 threads.
// ---------------------------------------------------------------------------
__global__ __launch_bounds__(64) void solve_kernel() {
    const int g = blockIdx.x;
    const int t = threadIdx.x;

    float vals[14];
    #pragma unroll
    for (int k = 0; k < 14; k++)
        vals[k] = g_part[((size_t)g * NB + t) * 14 + k];

    const int lane = t & 31;
    const int warp = t >> 5;
    #pragma unroll
    for (int k = 0; k < 14; k++) {
        #pragma unroll
        for (int o = 16; o > 0; o >>= 1)
            vals[k] += __shfl_down_sync(0xffffffffu, vals[k], o);
    }
    __shared__ float sm[2][14];
    if (lane == 0) {
        #pragma unroll
        for (int k = 0; k < 14; k++) sm[warp][k] = vals[k];
    }
    __syncthreads();

    if (t == 0) {
        double S[4], Q[10];
        #pragma unroll
        for (int k = 0; k < 4; k++) S[k] = (double)sm[0][k] + (double)sm[1][k];
        #pragma unroll
        for (int k = 0; k < 10; k++) Q[k] = (double)sm[0][4 + k] + (double)sm[1][4 + k];

        const double n = (double)NB * (double)SP;
        double m[4];
        #pragma unroll
        for (int k = 0; k < 4; k++) m[k] = S[k] / n;

        // centered covariance (unnormalized, matches torch.bmm(T,T^T))
        double A[4][4];
        const int qi[4][4] = {{0,1,2,3},{1,4,5,6},{2,5,7,8},{3,6,8,9}};
        for (int i = 0; i < 4; i++)
            for (int j = 0; j < 4; j++) {
                double c = Q[qi[i][j]] - n * m[i] * m[j];
                A[i][j] = (1.0 - EPSF) * c + (i == j ? EPSF : 0.0);
            }

        // Jacobi eigendecomposition: A = V D V^T
        double V[4][4] = {{1,0,0,0},{0,1,0,0},{0,0,1,0},{0,0,0,1}};
        for (int sweep = 0; sweep < 15; sweep++) {
            double off = fabs(A[0][1]) + fabs(A[0][2]) + fabs(A[0][3])
                       + fabs(A[1][2]) + fabs(A[1][3]) + fabs(A[2][3]);
            if (off < 1e-11 * (fabs(A[0][0]) + fabs(A[1][1]) + fabs(A[2][2]) + fabs(A[3][3]) + 1e-300))
                break;
            for (int p = 0; p < 3; p++)
                for (int q = p + 1; q < 4; q++) {
                    double apq = A[p][q];
                    if (fabs(apq) < 1e-300) continue;
                    double theta = (A[q][q] - A[p][p]) / (2.0 * apq);
                    double tt = (theta >= 0.0 ? 1.0 : -1.0) / (fabs(theta) + sqrt(theta * theta + 1.0));
                    double c = 1.0 / sqrt(tt * tt + 1.0);
                    double s = tt * c;
                    for (int k = 0; k < 4; k++) {
                        double akp = A[k][p], akq = A[k][q];
                        A[k][p] = c * akp - s * akq;
                        A[k][q] = s * akp + c * akq;
                    }
                    for (int k = 0; k < 4; k++) {
                        double apk = A[p][k], aqk = A[q][k];
                        A[p][k] = c * apk - s * aqk;
                        A[q][k] = s * apk + c * aqk;
                    }
                    for (int k = 0; k < 4; k++) {
                        double vkp = V[k][p], vkq = V[k][q];
                        V[k][p] = c * vkp - s * vkq;
                        V[k][q] = s * vkp + c * vkq;
                    }
                }
        }

        double inv[4];
        #pragma unroll
        for (int k = 0; k < 4; k++) inv[k] = 1.0 / sqrt(A[k][k] + EPSF);

        // W = V diag(inv) V^T ; bias = W m
        double W[4][4];
        for (int i = 0; i < 4; i++)
            for (int j = 0; j < 4; j++) {
                double w = 0.0;
                #pragma unroll
                for (int k = 0; k < 4; k++) w += V[i][k] * inv[k] * V[j][k];
                W[i][j] = w;
            }
        for (int i = 0; i < 4; i++) {
            double bsum = 0.0;
            #pragma unroll
            for (int j = 0; j < 4; j++) {
                g_W[g * 16 + i * 4 + j] = (float)W[i][j];
                bsum += W[i][j] * m[j];
            }
            g_bias[g * 4 + i] = (float)bsum;
        }
    }
}

// ---------------------------------------------------------------------------
// Pass 3: apply. grid (NG, NB), 256 threads.
// ---------------------------------------------------------------------------
struct WMat {
    float w00, w01, w02, w03;
    float w10, w11, w12, w13;
    float w20, w21, w22, w23;
    float w30, w31, w32, w33;
    float b0, b1, b2, b3;
};

__device__ __forceinline__ float4 fma4(float w, float4 v, float4 acc) {
    acc.x = fmaf(w, v.x, acc.x);
    acc.y = fmaf(w, v.y, acc.y);
    acc.z = fmaf(w, v.z, acc.z);
    acc.w = fmaf(w, v.w, acc.w);
    return acc;
}

__device__ __forceinline__ void apply_one(const WMat& W,
                                          float4 a, float4 e, float4 f, float4 h,
                                          float4& r0, float4& r1, float4& r2, float4& r3) {
    r0 = make_float4(-W.b0, -W.b0, -W.b0, -W.b0);
    r0 = fma4(W.w00, a, r0); r0 = fma4(W.w01, e, r0);
    r0 = fma4(W.w02, f, r0); r0 = fma4(W.w03, h, r0);
    r1 = make_float4(-W.b1, -W.b1, -W.b1, -W.b1);
    r1 = fma4(W.w10, a, r1); r1 = fma4(W.w11, e, r1);
    r1 = fma4(W.w12, f, r1); r1 = fma4(W.w13, h, r1);
    r2 = make_float4(-W.b2, -W.b2, -W.b2, -W.b2);
    r2 = fma4(W.w20, a, r2); r2 = fma4(W.w21, e, r2);
    r2 = fma4(W.w22, f, r2); r2 = fma4(W.w23, h, r2);
    r3 = make_float4(-W.b3, -W.b3, -W.b3, -W.b3);
    r3 = fma4(W.w30, a, r3); r3 = fma4(W.w31, e, r3);
    r3 = fma4(W.w32, f, r3); r3 = fma4(W.w33, h, r3);
}

__global__ __launch_bounds__(256) void apply_kernel(const float* __restrict__ x,
                                                    float* __restrict__ out) {
    const int g = blockIdx.x;
    const int b = blockIdx.y;
    const int tid = threadIdx.x;

    __shared__ float Ws[20];
    if (tid < 16) Ws[tid] = g_W[g * 16 + tid];
    if (tid < 4)  Ws[16 + tid] = g_bias[g * 4 + tid];
    __syncthreads();

    WMat W;
    W.w00 = Ws[0];  W.w01 = Ws[1];  W.w02 = Ws[2];  W.w03 = Ws[3];
    W.w10 = Ws[4];  W.w11 = Ws[5];  W.w12 = Ws[6];  W.w13 = Ws[7];
    W.w20 = Ws[8];  W.w21 = Ws[9];  W.w22 = Ws[10]; W.w23 = Ws[11];
    W.w30 = Ws[12]; W.w31 = Ws[13]; W.w32 = Ws[14]; W.w33 = Ws[15];
    W.b0 = Ws[16]; W.b1 = Ws[17]; W.b2 = Ws[18]; W.b3 = Ws[19];

    const size_t base = ((size_t)b * NCH + (size_t)g * 4) * SP;
    const float4* __restrict__ c0 = (const float4*)(x + base);
    const float4* __restrict__ c1 = c0 + SP4;
    const float4* __restrict__ c2 = c0 + 2 * SP4;
    const float4* __restrict__ c3 = c0 + 3 * SP4;
    float4* __restrict__ o0 = (float4*)(out + base);
    float4* __restrict__ o1 = o0 + SP4;
    float4* __restrict__ o2 = o0 + 2 * SP4;
    float4* __restrict__ o3 = o0 + 3 * SP4;

    // iterations 0 and 1 front-batched (8 independent LDG.128)
    {
        const int i0 = tid, i1 = tid + 256;
        float4 a0 = c0[i0], e0 = c1[i0], f0 = c2[i0], h0 = c3[i0];
        float4 a1 = c0[i1], e1 = c1[i1], f1 = c2[i1], h1 = c3[i1];
        float4 r0, r1, r2, r3;
        apply_one(W, a0, e0, f0, h0, r0, r1, r2, r3);
        o0[i0] = r0; o1[i0] = r1; o2[i0] = r2; o3[i0] = r3;
        apply_one(W, a1, e1, f1, h1, r0, r1, r2, r3);
        o0[i1] = r0; o1[i1] = r1; o2[i1] = r2; o3[i1] = r3;
    }
    // iteration 2 (full)
    {
        const int i2 = tid + 512;
        float4 a = c0[i2], e = c1[i2], f = c2[i2], h = c3[i2];
        float4 r0, r1, r2, r3;
        apply_one(W, a, e, f, h, r0, r1, r2, r3);
        o0[i2] = r0; o1[i2] = r1; o2[i2] = r2; o3[i2] = r3;
    }
    // tail: 16 elements
    if (tid < 16) {
        const int i3 = tid + 768;
        float4 a = c0[i3], e = c1[i3], f = c2[i3], h = c3[i3];
        float4 r0, r1, r2, r3;
        apply_one(W, a, e, f, h, r0, r1, r2, r3);
        o0[i3] = r0; o1[i3] = r1; o2[i3] = r2; o3[i3] = r3;
    }
}

// ---------------------------------------------------------------------------
extern "C" void kernel_launch(void* const* d_in, const int* in_sizes, int n_in,
                              void* d_out, int out_size) {
    const float* x = (const float*)d_in[0];
    float* out = (float*)d_out;

    dim3 grid(NG, NB);
    stats_kernel<<<grid, 256>>>(x);
    solve_kernel<<<NG, 64>>>();
    apply_kernel<<<grid, 256>>>(x, out);
}